// round 3
// baseline (speedup 1.0000x reference)
#include <cuda_runtime.h>
#include <cuda_bf16.h>

#define MAXN 50000
#define MAXE 800000

// Scratch (allocation-free: __device__ globals)
__device__ __align__(16) float g_xagg[MAXN * 2];    // A @ x           [N,2]
__device__ __align__(16) float g_t2[MAXN * 64];     // h1 @ W2         [N,64]
__device__ __align__(16) float g_h2agg[MAXN * 64];  // A @ t2          [N,64]
__device__ __align__(16) float g_t3[MAXN];          // h2 @ W3         [N,1]

// packed fp32x2 FMA: d = a*b + d   (sm_100+ only; ptxas never emits this from C++)
__device__ __forceinline__ void ffma2(unsigned long long& d,
                                      unsigned long long a,
                                      unsigned long long b) {
    asm("fma.rn.f32x2 %0, %1, %2, %0;" : "+l"(d) : "l"(a), "l"(b));
}

// K0: zero accumulators, init out = b3
__global__ void init_kernel(const float* __restrict__ b3, float* __restrict__ out, int n) {
    int i = blockIdx.x * blockDim.x + threadIdx.x;
    if (i < n * 64) g_h2agg[i] = 0.f;
    if (i < n * 2)  g_xagg[i]  = 0.f;
    if (i < n)      out[i]     = b3[0];
}

// K1: layer-1 aggregation BEFORE the GEMM: xagg[dst] += w * x[src]  (2 floats/edge)
__global__ void scatter1_kernel(const float* __restrict__ x,
                                const int* __restrict__ ei,
                                const float* __restrict__ ew, int e) {
    int idx = blockIdx.x * blockDim.x + threadIdx.x;
    if (idx >= e) return;
    int s = ei[idx];
    int d = ei[e + idx];
    float w = ew[idx];
    float2 xv = *(const float2*)(x + (long long)s * 2);
    float* p = g_xagg + (long long)d * 2;
    asm volatile("red.global.add.v2.f32 [%0], {%1,%2};"
                 :: "l"(p), "f"(w * xv.x), "f"(w * xv.y) : "memory");
}

// K2 (rewritten): t2 = relu(xagg@W1 + b1) @ W2.
// One node per thread; W1/b1/W2 staged in smem; 64 fp32 accumulators kept as
// 32 packed f32x2 registers updated with fma.rn.f32x2 (2 FLOP/inst).
// W2 row broadcast via LDS.128 (all lanes same address -> conflict-free).
__global__ __launch_bounds__(256) void dense12_kernel(const float* __restrict__ W1,
                                                      const float* __restrict__ b1,
                                                      const float* __restrict__ W2,
                                                      int n) {
    __shared__ float  sW1[256];     // [2][128]
    __shared__ float  sb1[128];
    __shared__ float4 sW2[2048];    // [128][16] float4 = [128][64] floats

    int tid = threadIdx.x;
    sW1[tid] = W1[tid];
    if (tid < 128) sb1[tid] = b1[tid];
    const float4* W2v = (const float4*)W2;
#pragma unroll
    for (int q = 0; q < 8; q++) sW2[q * 256 + tid] = W2v[q * 256 + tid];
    __syncthreads();

    int node = blockIdx.x * 256 + tid;
    if (node >= n) return;

    float x0 = g_xagg[node * 2 + 0];
    float x1 = g_xagg[node * 2 + 1];

    unsigned long long acc2[32];
#pragma unroll
    for (int q = 0; q < 32; q++) acc2[q] = 0ULL;  // {0.f, 0.f}

    for (int k = 0; k < 128; k++) {
        float h = fmaf(x0, sW1[k], fmaf(x1, sW1[128 + k], sb1[k]));
        h = fmaxf(h, 0.f);
        unsigned long long hh;
        asm("mov.b64 %0, {%1, %1};" : "=l"(hh) : "f"(h));
        const ulonglong2* row = (const ulonglong2*)(sW2 + k * 16);
#pragma unroll
        for (int q = 0; q < 16; q++) {
            ulonglong2 w = row[q];
            ffma2(acc2[2 * q + 0], w.x, hh);
            ffma2(acc2[2 * q + 1], w.y, hh);
        }
    }

    ulonglong2* op = (ulonglong2*)(g_t2 + (long long)node * 64);
#pragma unroll
    for (int q = 0; q < 16; q++)
        op[q] = make_ulonglong2(acc2[2 * q], acc2[2 * q + 1]);
}

// K3: layer-2 aggregation: h2agg[dst] += w * t2[src]  (64 floats/edge).
// 16 threads per edge, one red.global.add.v4.f32 each.
__global__ void scatter2_kernel(const int* __restrict__ ei,
                                const float* __restrict__ ew, int e) {
    int t = blockIdx.x * blockDim.x + threadIdx.x;
    if (t >= e * 16) return;
    int eidx = t >> 4;
    int c    = t & 15;
    int s = ei[eidx];
    int d = ei[e + eidx];
    float w = ew[eidx];
    float4 v = *(const float4*)(g_t2 + (long long)s * 64 + c * 4);
    float* p = g_h2agg + (long long)d * 64 + c * 4;
    asm volatile("red.global.add.v4.f32 [%0], {%1,%2,%3,%4};"
                 :: "l"(p), "f"(w * v.x), "f"(w * v.y), "f"(w * v.z), "f"(w * v.w)
                 : "memory");
}

// K4: t3 = relu(h2agg + b2) @ W3   (warp per node, shuffle reduce)
__global__ void dense3_kernel(const float* __restrict__ b2,
                              const float* __restrict__ W3, int n) {
    int gtid = blockIdx.x * blockDim.x + threadIdx.x;
    int node = gtid >> 5;
    int lane = gtid & 31;
    if (node >= n) return;
    const float* row = g_h2agg + (long long)node * 64;
    float a = fmaxf(row[lane] + b2[lane], 0.f) * W3[lane]
            + fmaxf(row[lane + 32] + b2[lane + 32], 0.f) * W3[lane + 32];
#pragma unroll
    for (int o = 16; o; o >>= 1) a += __shfl_xor_sync(0xffffffffu, a, o);
    if (lane == 0) g_t3[node] = a;
}

// K5: layer-3 aggregation straight into out (pre-initialized to b3): 1 float/edge
__global__ void scatter3_kernel(const int* __restrict__ ei,
                                const float* __restrict__ ew,
                                float* __restrict__ out, int e) {
    int idx = blockIdx.x * blockDim.x + threadIdx.x;
    if (idx >= e) return;
    int s = ei[idx];
    int d = ei[e + idx];
    atomicAdd(out + d, ew[idx] * g_t3[s]);
}

extern "C" void kernel_launch(void* const* d_in, const int* in_sizes, int n_in,
                              void* d_out, int out_size) {
    const float* x  = (const float*)d_in[0];
    const int*   ei = (const int*)d_in[1];
    const float* ew = (const float*)d_in[2];
    const float* W1 = (const float*)d_in[3];
    const float* b1 = (const float*)d_in[4];
    const float* W2 = (const float*)d_in[5];
    const float* b2 = (const float*)d_in[6];
    const float* W3 = (const float*)d_in[7];
    const float* b3 = (const float*)d_in[8];
    float* out = (float*)d_out;

    int n = in_sizes[0] / 2;   // 50000
    int e = in_sizes[2];       // 800000

    init_kernel<<<(n * 64 + 255) / 256, 256>>>(b3, out, n);
    scatter1_kernel<<<(e + 255) / 256, 256>>>(x, ei, ew, e);
    dense12_kernel<<<(n + 255) / 256, 256>>>(W1, b1, W2, n);
    long long total2 = (long long)e * 16;
    scatter2_kernel<<<(int)((total2 + 255) / 256), 256>>>(ei, ew, e);
    dense3_kernel<<<(n * 32 + 255) / 256, 256>>>(b2, W3, n);
    scatter3_kernel<<<(e + 255) / 256, 256>>>(ei, ew, out, e);
}

// round 4
// speedup vs baseline: 1.5661x; 1.5661x over previous
#include <cuda_runtime.h>
#include <cuda_bf16.h>

#define MAXN 50000
#define MAXE 800000
#define SCAN_BLK 256

// ── Scratch (allocation-free: __device__ globals) ───────────────────────────
__device__ int  g_deg[MAXN];              // degree of each dst node
__device__ int  g_part[MAXN];             // block-local exclusive scan
__device__ int  g_bsum[SCAN_BLK];         // per-block sums (<=256 blocks)
__device__ int  g_off[MAXN];              // CSR row offsets (exclusive scan)
__device__ int  g_cur[MAXN];              // fill cursors
__device__ __align__(8)  int2  g_csr[MAXE];   // per dst: {src, bitcast(w)}
__device__ __align__(16) float g_t2[MAXN * 64];  // relu(xagg@W1+b1)@W2
__device__ __align__(4)  float g_t3[MAXN];       // relu(h2agg+b2)@W3

// packed fp32x2 FMA: d = a*b + d (sm_100+; ptxas never emits from C++)
__device__ __forceinline__ void ffma2(unsigned long long& d,
                                      unsigned long long a,
                                      unsigned long long b) {
    asm("fma.rn.f32x2 %0, %1, %2, %0;" : "+l"(d) : "l"(a), "l"(b));
}

// ── CSR build ───────────────────────────────────────────────────────────────
__global__ void zero_deg_kernel(int n) {
    int i = blockIdx.x * blockDim.x + threadIdx.x;
    if (i < n) g_deg[i] = 0;
}

__global__ void hist_kernel(const int* __restrict__ ei, int e) {
    int i = blockIdx.x * blockDim.x + threadIdx.x;
    if (i < e) atomicAdd(&g_deg[ei[e + i]], 1);   // dst
}

__global__ void scan1_kernel(int n) {
    __shared__ int sh[SCAN_BLK];
    int tid = threadIdx.x;
    int i = blockIdx.x * SCAN_BLK + tid;
    int v = (i < n) ? g_deg[i] : 0;
    sh[tid] = v;
    __syncthreads();
#pragma unroll
    for (int o = 1; o < SCAN_BLK; o <<= 1) {
        int t = (tid >= o) ? sh[tid - o] : 0;
        __syncthreads();
        sh[tid] += t;
        __syncthreads();
    }
    if (i < n) g_part[i] = sh[tid] - v;           // exclusive within block
    if (tid == SCAN_BLK - 1) g_bsum[blockIdx.x] = sh[tid];
}

__global__ void scan2_kernel(int nb) {            // nb <= 256, one block
    __shared__ int sh[SCAN_BLK];
    int tid = threadIdx.x;
    int v = (tid < nb) ? g_bsum[tid] : 0;
    sh[tid] = v;
    __syncthreads();
#pragma unroll
    for (int o = 1; o < SCAN_BLK; o <<= 1) {
        int t = (tid >= o) ? sh[tid - o] : 0;
        __syncthreads();
        sh[tid] += t;
        __syncthreads();
    }
    if (tid < nb) g_bsum[tid] = sh[tid] - v;      // exclusive
}

__global__ void scan3_kernel(int n) {
    int i = blockIdx.x * SCAN_BLK + threadIdx.x;
    if (i < n) {
        int o = g_part[i] + g_bsum[blockIdx.x];
        g_off[i] = o;
        g_cur[i] = o;
    }
}

__global__ void fill_kernel(const int* __restrict__ ei,
                            const float* __restrict__ ew, int e) {
    int i = blockIdx.x * blockDim.x + threadIdx.x;
    if (i >= e) return;
    int s = ei[i];
    int d = ei[e + i];
    int pos = atomicAdd(&g_cur[d], 1);
    g_csr[pos] = make_int2(s, __float_as_int(ew[i]));
}

// ── Fused layer 1+2 dense: gather xagg per node, then t2 = relu(xagg@W1+b1)@W2
// One node per thread; weights staged in smem; 64 accumulators as 32 f32x2.
__global__ __launch_bounds__(256) void dense12_kernel(const float* __restrict__ x,
                                                      const float* __restrict__ W1,
                                                      const float* __restrict__ b1,
                                                      const float* __restrict__ W2,
                                                      int n) {
    __shared__ float  sW1[256];     // [2][128]
    __shared__ float  sb1[128];
    __shared__ float4 sW2[2048];    // [128][16] float4

    int tid = threadIdx.x;
    sW1[tid] = W1[tid];
    if (tid < 128) sb1[tid] = b1[tid];
    const float4* W2v = (const float4*)W2;
#pragma unroll
    for (int q = 0; q < 8; q++) sW2[q * 256 + tid] = W2v[q * 256 + tid];
    __syncthreads();

    int node = blockIdx.x * 256 + tid;
    if (node >= n) return;

    // layer-1 aggregation as gather (2 floats/edge)
    int beg = g_off[node];
    int dg  = g_deg[node];
    float x0 = 0.f, x1 = 0.f;
    for (int j = 0; j < dg; j++) {
        int2 ed = g_csr[beg + j];
        float w = __int_as_float(ed.y);
        float2 xv = *(const float2*)(x + (long long)ed.x * 2);
        x0 = fmaf(w, xv.x, x0);
        x1 = fmaf(w, xv.y, x1);
    }

    unsigned long long acc2[32];
#pragma unroll
    for (int q = 0; q < 32; q++) acc2[q] = 0ULL;

    for (int k = 0; k < 128; k++) {
        float h = fmaf(x0, sW1[k], fmaf(x1, sW1[128 + k], sb1[k]));
        h = fmaxf(h, 0.f);
        unsigned long long hh;
        asm("mov.b64 %0, {%1, %1};" : "=l"(hh) : "f"(h));
        const ulonglong2* row = (const ulonglong2*)(sW2 + k * 16);
#pragma unroll
        for (int q = 0; q < 16; q++) {
            ulonglong2 w = row[q];
            ffma2(acc2[2 * q + 0], w.x, hh);
            ffma2(acc2[2 * q + 1], w.y, hh);
        }
    }

    ulonglong2* op = (ulonglong2*)(g_t2 + (long long)node * 64);
#pragma unroll
    for (int q = 0; q < 16; q++)
        op[q] = make_ulonglong2(acc2[2 * q], acc2[2 * q + 1]);
}

// ── Fused layer-2 aggregation + layer-3 dense: warp per dst node.
// Lane l owns channels {2l, 2l+1}; coalesced 256B row reads of g_t2.
// Epilogue: relu(+b2) dot W3, shuffle reduce -> g_t3.
__global__ __launch_bounds__(256) void gd23_kernel(const float* __restrict__ b2,
                                                   const float* __restrict__ W3,
                                                   int n) {
    int gtid = blockIdx.x * blockDim.x + threadIdx.x;
    int node = gtid >> 5;
    int lane = gtid & 31;
    if (node >= n) return;

    int beg = g_off[node];
    int dg  = g_deg[node];
    float a0 = 0.f, a1 = 0.f;
    for (int j = 0; j < dg; j++) {
        int2 ed = g_csr[beg + j];                  // warp-uniform broadcast load
        float w = __int_as_float(ed.y);
        float2 v = *(const float2*)(g_t2 + (long long)ed.x * 64 + lane * 2);
        a0 = fmaf(w, v.x, a0);
        a1 = fmaf(w, v.y, a1);
    }
    float r = fmaxf(a0 + b2[2 * lane], 0.f)     * W3[2 * lane]
            + fmaxf(a1 + b2[2 * lane + 1], 0.f) * W3[2 * lane + 1];
#pragma unroll
    for (int o = 16; o; o >>= 1) r += __shfl_xor_sync(0xffffffffu, r, o);
    if (lane == 0) g_t3[node] = r;
}

// ── Layer-3 aggregation as gather, straight into out (1 float/edge) ─────────
__global__ void gather3_kernel(const float* __restrict__ b3,
                               float* __restrict__ out, int n) {
    int node = blockIdx.x * blockDim.x + threadIdx.x;
    if (node >= n) return;
    int beg = g_off[node];
    int dg  = g_deg[node];
    float a = b3[0];
    for (int j = 0; j < dg; j++) {
        int2 ed = g_csr[beg + j];
        a = fmaf(__int_as_float(ed.y), g_t3[ed.x], a);
    }
    out[node] = a;
}

extern "C" void kernel_launch(void* const* d_in, const int* in_sizes, int n_in,
                              void* d_out, int out_size) {
    const float* x  = (const float*)d_in[0];
    const int*   ei = (const int*)d_in[1];
    const float* ew = (const float*)d_in[2];
    const float* W1 = (const float*)d_in[3];
    const float* b1 = (const float*)d_in[4];
    const float* W2 = (const float*)d_in[5];
    const float* b2 = (const float*)d_in[6];
    const float* W3 = (const float*)d_in[7];
    const float* b3 = (const float*)d_in[8];
    float* out = (float*)d_out;

    int n = in_sizes[0] / 2;   // 50000
    int e = in_sizes[2];       // 800000
    int nb = (n + SCAN_BLK - 1) / SCAN_BLK;   // 196 (<=256)

    zero_deg_kernel<<<nb, SCAN_BLK>>>(n);
    hist_kernel<<<(e + 255) / 256, 256>>>(ei, e);
    scan1_kernel<<<nb, SCAN_BLK>>>(n);
    scan2_kernel<<<1, SCAN_BLK>>>(nb);
    scan3_kernel<<<nb, SCAN_BLK>>>(n);
    fill_kernel<<<(e + 255) / 256, 256>>>(ei, ew, e);
    dense12_kernel<<<(n + 255) / 256, 256>>>(x, W1, b1, W2, n);
    gd23_kernel<<<(n * 32 + 255) / 256, 256>>>(b2, W3, n);
    gather3_kernel<<<(n + 255) / 256, 256>>>(b3, out, n);
}